// round 8
// baseline (speedup 1.0000x reference)
#include <cuda_runtime.h>
#include <cstdint>

// Problem dims (fixed by reference)
#define BSZ  8
#define SDIM 2048
#define IDIM 1024
#define HDIM 4096
#define ODIM 1024
#define MDIM (BSZ * SDIM)   // 16384

// Scratch (no cudaMalloc allowed)
__device__ float g_decay[(size_t)MDIM * IDIM];     // 64 MB
__device__ float g_combined[(size_t)MDIM * IDIM];  // 64 MB (tf32-rounded)
__device__ float g_hidden[(size_t)MDIM * HDIM];    // 256 MB (tf32-rounded)
__device__ float g_xr[(size_t)MDIM * IDIM];        // 64 MB (tf32-rounded x)
__device__ float g_wgr[(size_t)IDIM * IDIM];       // 4 MB
__device__ float g_w1r[(size_t)HDIM * IDIM];       // 16 MB
__device__ float g_w2r[(size_t)ODIM * HDIM];       // 16 MB

// tcgen05 only exists in the arch-specific (sm_103a) compilation pass.
#if !defined(__CUDA_ARCH__) || defined(__CUDA_ARCH_FEAT_SM103_ALL) || \
    defined(__CUDA_ARCH_FEAT_SM100_ALL) || defined(__CUDA_ARCH_SPECIFIC__)
#define KUSE_TC 1
#else
#define KUSE_TC 0
#endif

// ---------------------------------------------------------------------------
// Common helpers
// ---------------------------------------------------------------------------
__device__ __forceinline__ uint32_t smem_u32(const void* p) {
    return (uint32_t)__cvta_generic_to_shared(p);
}
__device__ __forceinline__ float to_tf32(float x) {
    float r;
    asm("cvt.rna.tf32.f32 %0, %1;" : "=f"(r) : "f"(x));
    return r;
}
__device__ __forceinline__ void cp16(uint32_t s, const void* g) {
    asm volatile("cp.async.cg.shared.global [%0], [%1], 16;" ::"r"(s), "l"(g));
}
__device__ __forceinline__ void cluster_sync() {
    asm volatile("barrier.cluster.arrive.aligned;" ::: "memory");
    asm volatile("barrier.cluster.wait.aligned;" ::: "memory");
}

#if KUSE_TC
__device__ __forceinline__ void mbar_init(uint32_t a, uint32_t cnt) {
    asm volatile("mbarrier.init.shared.b64 [%0], %1;" ::"r"(a), "r"(cnt)
                 : "memory");
}
__device__ __forceinline__ void mbar_wait(uint32_t a, uint32_t parity) {
    asm volatile(
        "{\n\t.reg .pred P;\n"
        "W%=:\n\t"
        "mbarrier.try_wait.parity.acquire.cta.shared::cta.b64 P, [%0], %1, 0x989680;\n\t"
        "@P bra D%=;\n\t"
        "bra W%=;\n"
        "D%=:\n\t}"
        ::"r"(a), "r"(parity)
        : "memory");
}
// Arrive on the same-offset mbarrier in cluster CTA `rank` (cross-CTA signal).
__device__ __forceinline__ void mbar_arrive_cluster(uint32_t a, uint32_t rank) {
    asm volatile(
        "{\n\t.reg .b32 ra;\n\t"
        "mapa.shared::cluster.u32 ra, %0, %1;\n\t"
        "mbarrier.arrive.shared::cluster.b64 _, [ra];\n\t}"
        ::"r"(a), "r"(rank)
        : "memory");
}
// cg2 tf32 SS MMA (M=256 across pair, B split N/2 per CTA)
__device__ __forceinline__ void mma_tf32_cg2(uint32_t d, uint64_t ad,
                                             uint64_t bd, uint32_t idesc,
                                             bool acc) {
    uint32_t en = acc ? 1u : 0u;
    asm volatile(
        "{\n\t.reg .pred p;\n\t"
        "setp.ne.u32 p, %4, 0;\n\t"
        "tcgen05.mma.cta_group::2.kind::tf32 [%0], %1, %2, %3, "
        "{%5,%5,%5,%5,%5,%5,%5,%5}, p;\n\t}"
        ::"r"(d), "l"(ad), "l"(bd), "r"(idesc), "r"(en), "r"(0u)
        : "memory");
}
#define LDTM_X32(r, a)                                                       \
    asm volatile(                                                            \
        "tcgen05.ld.sync.aligned.32x32b.x32.b32 "                            \
        "{%0,%1,%2,%3,%4,%5,%6,%7,%8,%9,%10,%11,%12,%13,%14,%15,"            \
        "%16,%17,%18,%19,%20,%21,%22,%23,%24,%25,%26,%27,%28,%29,%30,%31}, " \
        "[%32];"                                                             \
        : "=r"((r)[0]), "=r"((r)[1]), "=r"((r)[2]), "=r"((r)[3]),            \
          "=r"((r)[4]), "=r"((r)[5]), "=r"((r)[6]), "=r"((r)[7]),            \
          "=r"((r)[8]), "=r"((r)[9]), "=r"((r)[10]), "=r"((r)[11]),          \
          "=r"((r)[12]), "=r"((r)[13]), "=r"((r)[14]), "=r"((r)[15]),        \
          "=r"((r)[16]), "=r"((r)[17]), "=r"((r)[18]), "=r"((r)[19]),        \
          "=r"((r)[20]), "=r"((r)[21]), "=r"((r)[22]), "=r"((r)[23]),        \
          "=r"((r)[24]), "=r"((r)[25]), "=r"((r)[26]), "=r"((r)[27]),        \
          "=r"((r)[28]), "=r"((r)[29]), "=r"((r)[30]), "=r"((r)[31])         \
        : "r"(a))
#endif  // KUSE_TC

// ---------------------------------------------------------------------------
// GEMM: C[m,n] = act(sum_k A[m,k]*B[n,k] + bias[n])
// 2-CTA cluster tile 256(M) x 256(N), BK=32. Each CTA: 128 A-rows + 128
// B-rows (its N-half). 4-stage cp.async pipeline; rank 0 issues cg2 MMAs.
// ---------------------------------------------------------------------------
#define BM 256                 // M rows per cluster
#define BN 256                 // N cols per cluster
#define TB_A 16384             // 128 rows x 128 bytes
#define TB_B 16384             // 128 rows x 128 bytes
#define TB_ST (TB_A + TB_B)    // 32 KB per stage
#define STAGES 4
#define SMEM_REQ (STAGES * TB_ST + 1024 + 128)

static constexpr uint64_t DESC_BASE =
    (2ull << 61) | (1ull << 46) | (64ull << 32) | (1ull << 16);  // SW128 K-major
// idesc: dtype F32, a/btype TF32(2), N=256 total, M=256 total
#define IDESC ((1u << 4) | (2u << 7) | (2u << 10) | (32u << 17) | (16u << 24))

enum { EP_SIG = 0, EP_RELU = 1, EP_BIAS = 2 };

template <int EP, bool ROUND>
__global__ void __launch_bounds__(256, 1) __cluster_dims__(2, 1, 1)
gemm_tc(const float* __restrict__ A, const float* __restrict__ B,
        float* __restrict__ C, const float* __restrict__ bias, int M, int N,
        int K) {
    extern __shared__ char dsm[];
    const int tid  = threadIdx.x;
    const int warp = tid >> 5;
    const int lane = tid & 31;
    const int rank = blockIdx.x & 1;                 // cluster CTA rank
    const int bn   = (blockIdx.x >> 1) * BN;         // cluster N origin
    const int bm   = blockIdx.y * BM;                // cluster M origin
    const int am   = bm + rank * 128;                // my 128 A-rows
    const int bnr  = bn + rank * 128;                // my 128 B-rows (N half)

#if KUSE_TC
    // =================== tcgen05 cg2 path (sm_103a) =======================
    const uint32_t sb    = smem_u32(dsm);
    const uint32_t tiles = (sb + 1023u) & ~1023u;
    const uint32_t ctrl  = tiles + STAGES * TB_ST;
    const uint32_t FULLB = ctrl;                 // 4 x 8B (rank0 waits, cnt=2)
    const uint32_t DONEB = ctrl + 32;            // 4 x 8B (commit multicast)
    const uint32_t TPTR  = ctrl + 64;

    if (tid == 0) {
#pragma unroll
        for (int s = 0; s < STAGES; s++) {
            mbar_init(FULLB + 8 * s, 2);
            mbar_init(DONEB + 8 * s, 1);
        }
    }
    if (warp == 0) {
        asm volatile(
            "tcgen05.alloc.cta_group::2.sync.aligned.shared::cta.b32 [%0], %1;"
            ::"r"(TPTR), "r"(256u)
            : "memory");
        asm volatile("tcgen05.relinquish_alloc_permit.cta_group::2.sync.aligned;");
    }
    __syncthreads();
    cluster_sync();  // peer mbars initialized before any cross-CTA arrive
    uint32_t tmem;
    asm volatile("ld.shared.b32 %0, [%1];" : "=r"(tmem) : "r"(TPTR));

    const int nk = K >> 5;  // 32-float k-tiles

    auto load_tile = [&](int st, int kt) {
        const uint32_t As = tiles + st * TB_ST;
        const uint32_t Bs = As + TB_A;
        const float* Ag = A + (size_t)am * K + kt * 32;
        const float* Bg = B + (size_t)bnr * K + kt * 32;
#pragma unroll
        for (int t = 0; t < 4; t++) {
            const int ch = tid + t * 256;   // 0..1023
            const int r  = ch >> 3;         // row 0..127
            const int c  = ch & 7;          // 16B chunk
            uint32_t off = (uint32_t)(r * 128 + c * 16);
            off ^= (off >> 3) & 0x70;       // SW128 swizzle
            cp16(As + off, Ag + (size_t)r * K + c * 4);
            cp16(Bs + off, Bg + (size_t)r * K + c * 4);
        }
        asm volatile("cp.async.commit_group;");
    };

#pragma unroll
    for (int s = 0; s < STAGES - 1; s++) load_tile(s, s);

    for (int kt = 0; kt < nk; kt++) {
        const int st = kt % STAGES;
        asm volatile("cp.async.wait_group 2;");  // my tile kt resident
        __syncthreads();
        asm volatile("fence.proxy.async.shared::cta;" ::: "memory");
        if (tid == 0)  // signal rank0: my half of stage st is ready
            mbar_arrive_cluster(FULLB + 8 * st, 0);
        if (rank == 0 && tid == 0) {
            mbar_wait(FULLB + 8 * st, (uint32_t)((kt / STAGES) & 1));
            const uint32_t As = tiles + st * TB_ST;
            const uint64_t ad = DESC_BASE | ((uint64_t)(As >> 4) & 0x3FFF);
            const uint64_t bd =
                DESC_BASE | ((uint64_t)((As + TB_A) >> 4) & 0x3FFF);
#pragma unroll
            for (int s = 0; s < 4; s++)  // 4 x K=8 steps (+32B each)
                mma_tf32_cg2(tmem, ad + 2 * s, bd + 2 * s, IDESC,
                             (kt > 0) || (s > 0));
            asm volatile(
                "tcgen05.commit.cta_group::2.mbarrier::arrive::one."
                "shared::cluster.multicast::cluster.b64 [%0], %1;"
                ::"r"(DONEB + 8 * st), "h"((uint16_t)0x3)
                : "memory");
        }
        const int tl = kt + STAGES - 1;
        if (tl < nk) {
            if (tl >= STAGES)  // MMA that last read this buffer must be done
                mbar_wait(DONEB + 8 * (tl % STAGES),
                          (uint32_t)(((tl / STAGES) - 1) & 1));
            load_tile(tl % STAGES, tl);
        } else {
            asm volatile("cp.async.commit_group;");  // keep group count moving
        }
    }

    // drain: final tile's MMAs complete on both CTAs
    mbar_wait(DONEB + 8 * ((nk - 1) % STAGES),
              (uint32_t)(((nk / STAGES) - 1) & 1));
    asm volatile("tcgen05.fence::after_thread_sync;" ::: "memory");

    // ---- epilogue: my 128 rows x 256 cols from my TMEM ----
    const int wg  = warp >> 2;  // 0..1 -> 128-col half
    const int wq  = warp & 3;   // lane partition (rows)
    const uint32_t tpart = tmem + ((uint32_t)wq << 21);
    const int row = am + wq * 32 + lane;
#pragma unroll
    for (int h = 0; h < 4; h++) {
        const int col0 = wg * 128 + h * 32;
        uint32_t r[32];
        LDTM_X32(r, tpart + col0);
        asm volatile("tcgen05.wait::ld.sync.aligned;" ::: "memory");
        float v[32];
#pragma unroll
        for (int j = 0; j < 32; j++) {
            float t = __uint_as_float(r[j]) + __ldg(&bias[bn + col0 + j]);
            if (EP == EP_RELU) t = fmaxf(t, 0.0f);
            if (EP == EP_SIG) t = 1.0f / (1.0f + __expf(-t));
            if (ROUND) t = to_tf32(t);
            v[j] = t;
        }
        float* dst = &C[(size_t)row * N + bn + col0];
#pragma unroll
        for (int q = 0; q < 8; q++)
            *(float4*)&dst[q * 4] =
                make_float4(v[q * 4], v[q * 4 + 1], v[q * 4 + 2], v[q * 4 + 3]);
    }

    __syncthreads();
    if (warp == 0) {
        asm volatile("tcgen05.dealloc.cta_group::2.sync.aligned.b32 %0, %1;"
                     ::"r"(tmem), "r"(256u));
    }
    cluster_sync();

#else
    // ============ naive fallback (plain sm_103 pass; never runs) ==========
    for (int e = tid; e < 128 * BN; e += 256) {
        const int r  = e / BN;
        const int cc = e % BN;
        float acc = 0.0f;
        for (int k = 0; k < K; k++)
            acc += A[(size_t)(am + r) * K + k] * B[(size_t)(bn + cc) * K + k];
        float t = acc + bias[bn + cc];
        if (EP == EP_RELU) t = fmaxf(t, 0.0f);
        if (EP == EP_SIG) t = 1.0f / (1.0f + __expf(-t));
        if (ROUND) t = to_tf32(t);
        C[(size_t)(am + r) * N + bn + cc] = t;
    }
#endif  // KUSE_TC
}

// ---------------------------------------------------------------------------
// Round-to-nearest tf32 prep
// ---------------------------------------------------------------------------
__global__ void round_kernel(const float* __restrict__ in,
                             float* __restrict__ out, size_t n) {
    for (size_t i = (size_t)blockIdx.x * blockDim.x + threadIdx.x; i < n;
         i += (size_t)gridDim.x * blockDim.x)
        out[i] = to_tf32(in[i]);
}

// ---------------------------------------------------------------------------
// Sequential buffer scan; combined is tf32-rounded (GEMM A input).
// ---------------------------------------------------------------------------
__global__ void scan_kernel(const float* __restrict__ x,
                            const float* __restrict__ decay,
                            float* __restrict__ combined) {
    const int i = blockIdx.x * blockDim.x + threadIdx.x;
    const int b = blockIdx.y;
    const size_t base = (size_t)b * SDIM * IDIM + i;

    float buf = 0.0f;
    for (int t0 = 0; t0 < SDIM; t0 += 8) {
        float d[8], xv[8];
#pragma unroll
        for (int j = 0; j < 8; j++) {
            const size_t idx = base + (size_t)(t0 + j) * IDIM;
            d[j]  = decay[idx];
            xv[j] = x[idx];
        }
#pragma unroll
        for (int j = 0; j < 8; j++) {
            buf = buf * d[j] + (1.0f - d[j]) * xv[j];
            combined[base + (size_t)(t0 + j) * IDIM] = to_tf32(xv[j] * d[j] + buf);
        }
    }
}

// ---------------------------------------------------------------------------
// Launch
// ---------------------------------------------------------------------------
extern "C" void kernel_launch(void* const* d_in, const int* in_sizes, int n_in,
                              void* d_out, int out_size) {
    (void)in_sizes; (void)n_in; (void)out_size;
    const float* x  = (const float*)d_in[0];
    const float* W1 = (const float*)d_in[1];
    const float* b1 = (const float*)d_in[2];
    const float* W2 = (const float*)d_in[3];
    const float* b2 = (const float*)d_in[4];
    const float* Wg = (const float*)d_in[5];
    const float* bg = (const float*)d_in[6];
    float* out = (float*)d_out;

    void *pd, *pc, *ph, *pxr, *pwg, *pw1, *pw2;
    cudaGetSymbolAddress(&pd, g_decay);
    cudaGetSymbolAddress(&pc, g_combined);
    cudaGetSymbolAddress(&ph, g_hidden);
    cudaGetSymbolAddress(&pxr, g_xr);
    cudaGetSymbolAddress(&pwg, g_wgr);
    cudaGetSymbolAddress(&pw1, g_w1r);
    cudaGetSymbolAddress(&pw2, g_w2r);
    float* decay    = (float*)pd;
    float* combined = (float*)pc;
    float* hidden   = (float*)ph;
    float* xr       = (float*)pxr;
    float* wgr      = (float*)pwg;
    float* w1r      = (float*)pw1;
    float* w2r      = (float*)pw2;

    cudaFuncSetAttribute(gemm_tc<EP_SIG, false>,
                         cudaFuncAttributeMaxDynamicSharedMemorySize, SMEM_REQ);
    cudaFuncSetAttribute(gemm_tc<EP_RELU, true>,
                         cudaFuncAttributeMaxDynamicSharedMemorySize, SMEM_REQ);
    cudaFuncSetAttribute(gemm_tc<EP_BIAS, false>,
                         cudaFuncAttributeMaxDynamicSharedMemorySize, SMEM_REQ);

    // tf32 round-to-nearest prep (weights + x)
    round_kernel<<<1024, 256>>>(x, xr, (size_t)MDIM * IDIM);
    round_kernel<<<256, 256>>>(Wg, wgr, (size_t)IDIM * IDIM);
    round_kernel<<<512, 256>>>(W1, w1r, (size_t)HDIM * IDIM);
    round_kernel<<<512, 256>>>(W2, w2r, (size_t)ODIM * HDIM);

    // 1) decay = sigmoid(x @ Wg^T + bg)   grid.x = N/128 (2 CTAs per tile)
    gemm_tc<EP_SIG, false><<<dim3(IDIM / 128, MDIM / BM), 256, SMEM_REQ>>>(
        xr, wgr, decay, bg, MDIM, IDIM, IDIM);
    // 2) recurrence -> combined (tf32-rounded)
    scan_kernel<<<dim3(IDIM / 64, BSZ), 64>>>(x, decay, combined);
    // 3) hidden = relu(combined @ W1^T + b1), tf32-rounded
    gemm_tc<EP_RELU, true><<<dim3(HDIM / 128, MDIM / BM), 256, SMEM_REQ>>>(
        combined, w1r, hidden, b1, MDIM, HDIM, IDIM);
    // 4) out = hidden @ W2^T + b2
    gemm_tc<EP_BIAS, false><<<dim3(ODIM / 128, MDIM / BM), 256, SMEM_REQ>>>(
        hidden, w2r, out, b2, MDIM, ODIM, HDIM);
}

// round 9
// speedup vs baseline: 1.5425x; 1.5425x over previous
#include <cuda_runtime.h>
#include <cstdint>

// Problem dims (fixed by reference)
#define BSZ  8
#define SDIM 2048
#define IDIM 1024
#define HDIM 4096
#define ODIM 1024
#define MDIM (BSZ * SDIM)   // 16384

// Scratch (no cudaMalloc allowed)
__device__ float g_decay[(size_t)MDIM * IDIM];     // 64 MB
__device__ float g_combined[(size_t)MDIM * IDIM];  // 64 MB (tf32-rounded)
__device__ float g_hidden[(size_t)MDIM * HDIM];    // 256 MB (tf32-rounded)
__device__ float g_xr[(size_t)MDIM * IDIM];        // 64 MB (tf32-rounded x)
__device__ float g_wgr[(size_t)IDIM * IDIM];       // 4 MB
__device__ float g_w1r[(size_t)HDIM * IDIM];       // 16 MB
__device__ float g_w2r[(size_t)ODIM * HDIM];       // 16 MB

// tcgen05 only exists in the arch-specific (sm_103a) compilation pass.
#if !defined(__CUDA_ARCH__) || defined(__CUDA_ARCH_FEAT_SM103_ALL) || \
    defined(__CUDA_ARCH_FEAT_SM100_ALL) || defined(__CUDA_ARCH_SPECIFIC__)
#define KUSE_TC 1
#else
#define KUSE_TC 0
#endif

// ---------------------------------------------------------------------------
// Common helpers
// ---------------------------------------------------------------------------
__device__ __forceinline__ uint32_t smem_u32(const void* p) {
    return (uint32_t)__cvta_generic_to_shared(p);
}
__device__ __forceinline__ float to_tf32(float x) {
    float r;
    asm("cvt.rna.tf32.f32 %0, %1;" : "=f"(r) : "f"(x));
    return r;
}
__device__ __forceinline__ void cp16(uint32_t s, const void* g) {
    asm volatile("cp.async.cg.shared.global [%0], [%1], 16;" ::"r"(s), "l"(g));
}
__device__ __forceinline__ void cluster_sync() {
    asm volatile("barrier.cluster.arrive.aligned;" ::: "memory");
    asm volatile("barrier.cluster.wait.aligned;" ::: "memory");
}

#if KUSE_TC
__device__ __forceinline__ void mbar_init(uint32_t a, uint32_t cnt) {
    asm volatile("mbarrier.init.shared.b64 [%0], %1;" ::"r"(a), "r"(cnt)
                 : "memory");
}
__device__ __forceinline__ void mbar_wait(uint32_t a, uint32_t parity) {
    asm volatile(
        "{\n\t.reg .pred P;\n"
        "W%=:\n\t"
        "mbarrier.try_wait.parity.acquire.cta.shared::cta.b64 P, [%0], %1, 0x989680;\n\t"
        "@P bra D%=;\n\t"
        "bra W%=;\n"
        "D%=:\n\t}"
        ::"r"(a), "r"(parity)
        : "memory");
}
// Arrive on the same-offset mbarrier in cluster CTA `rank`.
__device__ __forceinline__ void mbar_arrive_cluster(uint32_t a, uint32_t rank) {
    asm volatile(
        "{\n\t.reg .b32 ra;\n\t"
        "mapa.shared::cluster.u32 ra, %0, %1;\n\t"
        "mbarrier.arrive.shared::cluster.b64 _, [ra];\n\t}"
        ::"r"(a), "r"(rank)
        : "memory");
}
// cg2 tf32 SS MMA (M=256 across pair, B split N/2 per CTA)
__device__ __forceinline__ void mma_tf32_cg2(uint32_t d, uint64_t ad,
                                             uint64_t bd, uint32_t idesc,
                                             bool acc) {
    uint32_t en = acc ? 1u : 0u;
    asm volatile(
        "{\n\t.reg .pred p;\n\t"
        "setp.ne.u32 p, %4, 0;\n\t"
        "tcgen05.mma.cta_group::2.kind::tf32 [%0], %1, %2, %3, "
        "{%5,%5,%5,%5,%5,%5,%5,%5}, p;\n\t}"
        ::"r"(d), "l"(ad), "l"(bd), "r"(idesc), "r"(en), "r"(0u)
        : "memory");
}
#define LDTM_X32(r, a)                                                       \
    asm volatile(                                                            \
        "tcgen05.ld.sync.aligned.32x32b.x32.b32 "                            \
        "{%0,%1,%2,%3,%4,%5,%6,%7,%8,%9,%10,%11,%12,%13,%14,%15,"            \
        "%16,%17,%18,%19,%20,%21,%22,%23,%24,%25,%26,%27,%28,%29,%30,%31}, " \
        "[%32];"                                                             \
        : "=r"((r)[0]), "=r"((r)[1]), "=r"((r)[2]), "=r"((r)[3]),            \
          "=r"((r)[4]), "=r"((r)[5]), "=r"((r)[6]), "=r"((r)[7]),            \
          "=r"((r)[8]), "=r"((r)[9]), "=r"((r)[10]), "=r"((r)[11]),          \
          "=r"((r)[12]), "=r"((r)[13]), "=r"((r)[14]), "=r"((r)[15]),        \
          "=r"((r)[16]), "=r"((r)[17]), "=r"((r)[18]), "=r"((r)[19]),        \
          "=r"((r)[20]), "=r"((r)[21]), "=r"((r)[22]), "=r"((r)[23]),        \
          "=r"((r)[24]), "=r"((r)[25]), "=r"((r)[26]), "=r"((r)[27]),        \
          "=r"((r)[28]), "=r"((r)[29]), "=r"((r)[30]), "=r"((r)[31])         \
        : "r"(a))
#endif  // KUSE_TC

// ---------------------------------------------------------------------------
// GEMM: C[m,n] = act(sum_k A[m,k]*B[n,k] + bias[n])
// 2-CTA cluster tile 256(M) x 256(N), BK=32. Warp-specialized:
//   warps 0-7 (256 thr): cp.async producers + epilogue
//   warp 8: MMA control (rank 0 only)
// 6-stage pipeline. Producers signal tile readiness with lag 2; MMA warp
// consumes FULLB (2 arrivals) and commits DONEB (multicast both CTAs).
// ---------------------------------------------------------------------------
#define BM 256                 // M rows per cluster
#define BN 256                 // N cols per cluster
#define TB_A 16384             // 128 rows x 128 bytes
#define TB_B 16384             // 128 rows x 128 bytes
#define TB_ST (TB_A + TB_B)    // 32 KB per stage
#define STAGES 6
#define NTHR 288
#define SMEM_REQ (STAGES * TB_ST + 1024 + 128)

static constexpr uint64_t DESC_BASE =
    (2ull << 61) | (1ull << 46) | (64ull << 32) | (1ull << 16);  // SW128 K-major
// idesc: dtype F32, a/btype TF32(2), N=256 total, M=256 total
#define IDESC ((1u << 4) | (2u << 7) | (2u << 10) | (32u << 17) | (16u << 24))

enum { EP_SIG = 0, EP_RELU = 1, EP_BIAS = 2 };

template <int EP, bool ROUND>
__global__ void __launch_bounds__(NTHR, 1) __cluster_dims__(2, 1, 1)
gemm_tc(const float* __restrict__ A, const float* __restrict__ B,
        float* __restrict__ C, const float* __restrict__ bias, int M, int N,
        int K) {
    extern __shared__ char dsm[];
    const int tid  = threadIdx.x;
    const int warp = tid >> 5;
    const int lane = tid & 31;
    const int rank = blockIdx.x & 1;                 // cluster CTA rank
    const int bn   = (blockIdx.x >> 1) * BN;         // cluster N origin
    const int bm   = blockIdx.y * BM;                // cluster M origin
    const int am   = bm + rank * 128;                // my 128 A-rows
    const int bnr  = bn + rank * 128;                // my 128 B-rows (N half)

#if KUSE_TC
    const uint32_t sb    = smem_u32(dsm);
    const uint32_t tiles = (sb + 1023u) & ~1023u;
    const uint32_t ctrl  = tiles + STAGES * TB_ST;
    const uint32_t FULLB = ctrl;                 // STAGES x 8B, cnt=2
    const uint32_t DONEB = ctrl + 8 * STAGES;    // STAGES x 8B, cnt=1
    const uint32_t TPTR  = ctrl + 16 * STAGES;

    if (tid == 0) {
#pragma unroll
        for (int s = 0; s < STAGES; s++) {
            mbar_init(FULLB + 8 * s, 2);
            mbar_init(DONEB + 8 * s, 1);
        }
    }
    if (warp == 0) {
        asm volatile(
            "tcgen05.alloc.cta_group::2.sync.aligned.shared::cta.b32 [%0], %1;"
            ::"r"(TPTR), "r"(256u)
            : "memory");
        asm volatile("tcgen05.relinquish_alloc_permit.cta_group::2.sync.aligned;");
    }
    __syncthreads();
    cluster_sync();  // peer mbars initialized before any cross-CTA arrive
    uint32_t tmem;
    asm volatile("ld.shared.b32 %0, [%1];" : "=r"(tmem) : "r"(TPTR));

    const int nk = K >> 5;  // 32-float k-tiles

    if (tid < 256) {
        // ===================== PRODUCERS (warps 0-7) ======================
        auto load_tile = [&](int st, int kt) {
            const uint32_t As = tiles + st * TB_ST;
            const uint32_t Bs = As + TB_A;
            const float* Ag = A + (size_t)am * K + kt * 32;
            const float* Bg = B + (size_t)bnr * K + kt * 32;
#pragma unroll
            for (int t = 0; t < 4; t++) {
                const int ch = tid + t * 256;   // 0..1023
                const int r  = ch >> 3;         // row 0..127
                const int c  = ch & 7;          // 16B chunk
                uint32_t off = (uint32_t)(r * 128 + c * 16);
                off ^= (off >> 3) & 0x70;       // SW128 swizzle
                cp16(As + off, Ag + (size_t)r * K + c * 4);
                cp16(Bs + off, Bg + (size_t)r * K + c * 4);
            }
            asm volatile("cp.async.commit_group;");
        };

        for (int lt = 0; lt < nk; lt++) {
            const int st = lt % STAGES;
            if (lt >= STAGES)  // buffer st last read by MMA of tile lt-STAGES
                mbar_wait(DONEB + 8 * st, (uint32_t)(((lt / STAGES) - 1) & 1));
            load_tile(st, lt);
            if (lt >= 2) {  // groups <= lt-2 complete -> tile lt-2 resident
                asm volatile("cp.async.wait_group 2;");
                asm volatile("fence.proxy.async.shared::cta;" ::: "memory");
                asm volatile("bar.sync 1, 256;" ::: "memory");
                if (tid == 0)
                    mbar_arrive_cluster(FULLB + 8 * ((lt - 2) % STAGES), 0);
            }
        }
        // drain: signal last two tiles
        asm volatile("cp.async.wait_group 1;");
        asm volatile("fence.proxy.async.shared::cta;" ::: "memory");
        asm volatile("bar.sync 1, 256;" ::: "memory");
        if (tid == 0)
            mbar_arrive_cluster(FULLB + 8 * ((nk - 2) % STAGES), 0);
        asm volatile("cp.async.wait_group 0;");
        asm volatile("fence.proxy.async.shared::cta;" ::: "memory");
        asm volatile("bar.sync 1, 256;" ::: "memory");
        if (tid == 0)
            mbar_arrive_cluster(FULLB + 8 * ((nk - 1) % STAGES), 0);
    } else if (rank == 0 && tid == 256) {
        // ===================== MMA CONTROL (warp 8, rank 0) ===============
        for (int kt = 0; kt < nk; kt++) {
            const int st = kt % STAGES;
            mbar_wait(FULLB + 8 * st, (uint32_t)((kt / STAGES) & 1));
            const uint32_t As = tiles + st * TB_ST;
            const uint64_t ad = DESC_BASE | ((uint64_t)(As >> 4) & 0x3FFF);
            const uint64_t bd =
                DESC_BASE | ((uint64_t)((As + TB_A) >> 4) & 0x3FFF);
#pragma unroll
            for (int s = 0; s < 4; s++)  // 4 x K=8 steps (+32B each)
                mma_tf32_cg2(tmem, ad + 2 * s, bd + 2 * s, IDESC,
                             (kt > 0) || (s > 0));
            asm volatile(
                "tcgen05.commit.cta_group::2.mbarrier::arrive::one."
                "shared::cluster.multicast::cluster.b64 [%0], %1;"
                ::"r"(DONEB + 8 * st), "h"((uint16_t)0x3)
                : "memory");
        }
    }

    // ---- epilogue (warps 0-7): my 128 rows x 256 cols from my TMEM ----
    if (tid < 256) {
        mbar_wait(DONEB + 8 * ((nk - 1) % STAGES),
                  (uint32_t)(((nk - 1) / STAGES) & 1));
        asm volatile("tcgen05.fence::after_thread_sync;" ::: "memory");

        const int wg  = warp >> 2;  // 0..1 -> 128-col half
        const int wq  = warp & 3;   // lane partition (rows)
        const uint32_t tpart = tmem + ((uint32_t)wq << 21);
        const int row = am + wq * 32 + lane;
#pragma unroll
        for (int h = 0; h < 4; h++) {
            const int col0 = wg * 128 + h * 32;
            uint32_t r[32];
            LDTM_X32(r, tpart + col0);
            asm volatile("tcgen05.wait::ld.sync.aligned;" ::: "memory");
            float v[32];
#pragma unroll
            for (int j = 0; j < 32; j++) {
                float t = __uint_as_float(r[j]) + __ldg(&bias[bn + col0 + j]);
                if (EP == EP_RELU) t = fmaxf(t, 0.0f);
                if (EP == EP_SIG) t = 1.0f / (1.0f + __expf(-t));
                if (ROUND) t = to_tf32(t);
                v[j] = t;
            }
            float* dst = &C[(size_t)row * N + bn + col0];
#pragma unroll
            for (int q = 0; q < 8; q++)
                *(float4*)&dst[q * 4] = make_float4(v[q * 4], v[q * 4 + 1],
                                                    v[q * 4 + 2], v[q * 4 + 3]);
        }
    }

    __syncthreads();
    if (warp == 0) {
        asm volatile("tcgen05.dealloc.cta_group::2.sync.aligned.b32 %0, %1;"
                     ::"r"(tmem), "r"(256u));
    }
    cluster_sync();

#else
    // ============ naive fallback (plain sm_103 pass; never runs) ==========
    for (int e = tid; e < 128 * BN; e += NTHR) {
        const int r  = e / BN;
        const int cc = e % BN;
        float acc = 0.0f;
        for (int k = 0; k < K; k++)
            acc += A[(size_t)(am + r) * K + k] * B[(size_t)(bn + cc) * K + k];
        float t = acc + bias[bn + cc];
        if (EP == EP_RELU) t = fmaxf(t, 0.0f);
        if (EP == EP_SIG) t = 1.0f / (1.0f + __expf(-t));
        if (ROUND) t = to_tf32(t);
        C[(size_t)(am + r) * N + bn + cc] = t;
    }
#endif  // KUSE_TC
}

// ---------------------------------------------------------------------------
// Round-to-nearest tf32 prep
// ---------------------------------------------------------------------------
__global__ void round_kernel(const float* __restrict__ in,
                             float* __restrict__ out, size_t n) {
    for (size_t i = (size_t)blockIdx.x * blockDim.x + threadIdx.x; i < n;
         i += (size_t)gridDim.x * blockDim.x)
        out[i] = to_tf32(in[i]);
}

// ---------------------------------------------------------------------------
// Sequential buffer scan; combined is tf32-rounded (GEMM A input).
// ---------------------------------------------------------------------------
__global__ void scan_kernel(const float* __restrict__ x,
                            const float* __restrict__ decay,
                            float* __restrict__ combined) {
    const int i = blockIdx.x * blockDim.x + threadIdx.x;
    const int b = blockIdx.y;
    const size_t base = (size_t)b * SDIM * IDIM + i;

    float buf = 0.0f;
    for (int t0 = 0; t0 < SDIM; t0 += 8) {
        float d[8], xv[8];
#pragma unroll
        for (int j = 0; j < 8; j++) {
            const size_t idx = base + (size_t)(t0 + j) * IDIM;
            d[j]  = decay[idx];
            xv[j] = x[idx];
        }
#pragma unroll
        for (int j = 0; j < 8; j++) {
            buf = buf * d[j] + (1.0f - d[j]) * xv[j];
            combined[base + (size_t)(t0 + j) * IDIM] = to_tf32(xv[j] * d[j] + buf);
        }
    }
}

// ---------------------------------------------------------------------------
// Launch
// ---------------------------------------------------------------------------
extern "C" void kernel_launch(void* const* d_in, const int* in_sizes, int n_in,
                              void* d_out, int out_size) {
    (void)in_sizes; (void)n_in; (void)out_size;
    const float* x  = (const float*)d_in[0];
    const float* W1 = (const float*)d_in[1];
    const float* b1 = (const float*)d_in[2];
    const float* W2 = (const float*)d_in[3];
    const float* b2 = (const float*)d_in[4];
    const float* Wg = (const float*)d_in[5];
    const float* bg = (const float*)d_in[6];
    float* out = (float*)d_out;

    void *pd, *pc, *ph, *pxr, *pwg, *pw1, *pw2;
    cudaGetSymbolAddress(&pd, g_decay);
    cudaGetSymbolAddress(&pc, g_combined);
    cudaGetSymbolAddress(&ph, g_hidden);
    cudaGetSymbolAddress(&pxr, g_xr);
    cudaGetSymbolAddress(&pwg, g_wgr);
    cudaGetSymbolAddress(&pw1, g_w1r);
    cudaGetSymbolAddress(&pw2, g_w2r);
    float* decay    = (float*)pd;
    float* combined = (float*)pc;
    float* hidden   = (float*)ph;
    float* xr       = (float*)pxr;
    float* wgr      = (float*)pwg;
    float* w1r      = (float*)pw1;
    float* w2r      = (float*)pw2;

    cudaFuncSetAttribute(gemm_tc<EP_SIG, false>,
                         cudaFuncAttributeMaxDynamicSharedMemorySize, SMEM_REQ);
    cudaFuncSetAttribute(gemm_tc<EP_RELU, true>,
                         cudaFuncAttributeMaxDynamicSharedMemorySize, SMEM_REQ);
    cudaFuncSetAttribute(gemm_tc<EP_BIAS, false>,
                         cudaFuncAttributeMaxDynamicSharedMemorySize, SMEM_REQ);

    // tf32 round-to-nearest prep (weights + x)
    round_kernel<<<1024, 256>>>(x, xr, (size_t)MDIM * IDIM);
    round_kernel<<<256, 256>>>(Wg, wgr, (size_t)IDIM * IDIM);
    round_kernel<<<512, 256>>>(W1, w1r, (size_t)HDIM * IDIM);
    round_kernel<<<512, 256>>>(W2, w2r, (size_t)ODIM * HDIM);

    // 1) decay = sigmoid(x @ Wg^T + bg)   grid.x = N/128 (2 CTAs per tile)
    gemm_tc<EP_SIG, false><<<dim3(IDIM / 128, MDIM / BM), NTHR, SMEM_REQ>>>(
        xr, wgr, decay, bg, MDIM, IDIM, IDIM);
    // 2) recurrence -> combined (tf32-rounded)
    scan_kernel<<<dim3(IDIM / 64, BSZ), 64>>>(x, decay, combined);
    // 3) hidden = relu(combined @ W1^T + b1), tf32-rounded
    gemm_tc<EP_RELU, true><<<dim3(HDIM / 128, MDIM / BM), NTHR, SMEM_REQ>>>(
        combined, w1r, hidden, b1, MDIM, HDIM, IDIM);
    // 4) out = hidden @ W2^T + b2
    gemm_tc<EP_BIAS, false><<<dim3(ODIM / 128, MDIM / BM), NTHR, SMEM_REQ>>>(
        hidden, w2r, out, b2, MDIM, ODIM, HDIM);
}